// round 1
// baseline (speedup 1.0000x reference)
#include <cuda_runtime.h>

// Problem shape (fixed by setup_inputs): BATCH=16384, P=16, D=2048
#define BATCH   16384
#define PNUM    16
#define DIM     2048
#define NGROUP  (BATCH / PNUM)     // 1024
#define D4      (DIM / 4)          // 512 float4 per row
#define THREADS 256
#define COLS_PT (D4 / THREADS)     // 2 float4 columns per thread

// Device-global scratch accumulator (no allocations allowed).
__device__ double g_acc;

__global__ void fl_zero_acc() { g_acc = 0.0; }

__global__ __launch_bounds__(THREADS) void fl_group_kernel(const float4* __restrict__ f) {
    const int g = blockIdx.x;
    const float4* base = f + (size_t)g * PNUM * D4;

    float ssq  = 0.0f;  // sum of element^2 over this thread's slice (B_g partial)
    float scol = 0.0f;  // sum of (column-sum)^2 over this thread's cols (A_g partial)

    #pragma unroll
    for (int k = 0; k < COLS_PT; k++) {
        const int c = threadIdx.x + k * THREADS;
        float4 cs = make_float4(0.f, 0.f, 0.f, 0.f);
        #pragma unroll
        for (int r = 0; r < PNUM; r++) {
            float4 v = base[r * D4 + c];
            cs.x += v.x; cs.y += v.y; cs.z += v.z; cs.w += v.w;
            ssq  += v.x * v.x + v.y * v.y + v.z * v.z + v.w * v.w;
        }
        scol += cs.x * cs.x + cs.y * cs.y + cs.z * cs.z + cs.w * cs.w;
    }

    // Contribution to Σ_g (B_g - A_g)
    double d = (double)(ssq - scol);

    // warp reduce (double via two-shuffle)
    #pragma unroll
    for (int o = 16; o; o >>= 1)
        d += __shfl_xor_sync(0xffffffffu, d, o);

    __shared__ double sh[THREADS / 32];
    if ((threadIdx.x & 31) == 0) sh[threadIdx.x >> 5] = d;
    __syncthreads();

    if (threadIdx.x < THREADS / 32) {
        double b = sh[threadIdx.x];
        #pragma unroll
        for (int o = (THREADS / 64); o; o >>= 1)
            b += __shfl_xor_sync(0xffu, b, o);
        if (threadIdx.x == 0)
            atomicAdd(&g_acc, b);
    }
}

__global__ void fl_finalize(float* out) {
    const double pairs = (double)PNUM * (PNUM - 1) / 2.0;  // 120
    out[0] = (float)(1.0 + g_acc / (2.0 * pairs * (double)NGROUP));
}

extern "C" void kernel_launch(void* const* d_in, const int* in_sizes, int n_in,
                              void* d_out, int out_size) {
    (void)in_sizes; (void)n_in; (void)out_size;
    const float4* f = (const float4*)d_in[0];
    float* out = (float*)d_out;

    fl_zero_acc<<<1, 1>>>();
    fl_group_kernel<<<NGROUP, THREADS>>>(f);
    fl_finalize<<<1, 1>>>(out);
}

// round 2
// speedup vs baseline: 1.0837x; 1.0837x over previous
#include <cuda_runtime.h>

// Problem shape (fixed by setup_inputs): BATCH=16384, P=16, D=2048
#define BATCH   16384
#define PNUM    16
#define DIM     2048
#define NGROUP  (BATCH / PNUM)     // 1024
#define D4      (DIM / 4)          // 512 float4 per row
#define THREADS 256
#define COLS_PT (D4 / THREADS)     // 2 float4 columns per thread

// Device-global scratch (statically zero-initialized; the finalizing block
// resets it each run, so every kernel_launch sees zeroed state -> deterministic
// and graph-replay safe, with no separate init launch).
__device__ double        g_acc   = 0.0;
__device__ unsigned int  g_count = 0u;

__global__ __launch_bounds__(THREADS) void fl_fused_kernel(const float4* __restrict__ f,
                                                           float* __restrict__ out) {
    const int g = blockIdx.x;
    const float4* base = f + (size_t)g * PNUM * D4;

    float ssq  = 0.0f;  // sum of element^2 (B_g partial)
    float scol = 0.0f;  // sum of (column-sum)^2 (A_g partial)

    #pragma unroll
    for (int k = 0; k < COLS_PT; k++) {
        const int c = threadIdx.x + k * THREADS;
        float4 cs = make_float4(0.f, 0.f, 0.f, 0.f);
        #pragma unroll
        for (int r = 0; r < PNUM; r++) {
            float4 v = base[r * D4 + c];
            cs.x += v.x; cs.y += v.y; cs.z += v.z; cs.w += v.w;
            ssq  += v.x * v.x + v.y * v.y + v.z * v.z + v.w * v.w;
        }
        scol += cs.x * cs.x + cs.y * cs.y + cs.z * cs.z + cs.w * cs.w;
    }

    // Contribution to sum_g (B_g - A_g)
    double d = (double)(ssq - scol);

    // warp reduce
    #pragma unroll
    for (int o = 16; o; o >>= 1)
        d += __shfl_xor_sync(0xffffffffu, d, o);

    __shared__ double sh[THREADS / 32];
    __shared__ bool s_last;
    if ((threadIdx.x & 31) == 0) sh[threadIdx.x >> 5] = d;
    __syncthreads();

    if (threadIdx.x == 0) {
        double b = 0.0;
        #pragma unroll
        for (int w = 0; w < THREADS / 32; w++) b += sh[w];
        atomicAdd(&g_acc, b);
        __threadfence();
        unsigned int ticket = atomicAdd(&g_count, 1u);
        s_last = (ticket == NGROUP - 1u);
        if (s_last) {
            const double pairs = (double)PNUM * (PNUM - 1) / 2.0;  // 120
            double acc = g_acc;                                     // all adds visible
            out[0] = (float)(1.0 + acc / (2.0 * pairs * (double)NGROUP));
            // reset for the next invocation / graph replay
            g_acc   = 0.0;
            g_count = 0u;
        }
    }
}

extern "C" void kernel_launch(void* const* d_in, const int* in_sizes, int n_in,
                              void* d_out, int out_size) {
    (void)in_sizes; (void)n_in; (void)out_size;
    const float4* f = (const float4*)d_in[0];
    float* out = (float*)d_out;
    fl_fused_kernel<<<NGROUP, THREADS>>>(f, out);
}